// round 16
// baseline (speedup 1.0000x reference)
#include <cuda_runtime.h>

// B=8, L=512, E=H=1024, K=16, 4H=4096
typedef unsigned long long u64;

// ---------------- scratch (static __device__; no allocations) ----------------
__device__ float g_G[2][4096][4096];                      // input projections + bias
__device__ __align__(16) unsigned short g_hb[2][2][8][1024]; // h double-buffered, bf16 [buf][dir][b][n]
__device__ float g_hout[2][8][512][1024];                 // h outputs at original positions (fp32)
__device__ float g_emit[8][512][16];                      // emissions
__device__ unsigned g_flag[2][64][32];                    // arrive-count flags (128B padded)

__device__ __forceinline__ float fast_sigmoid(float x){
    return 1.f / (1.f + __expf(-x));
}
__device__ __forceinline__ float fast_tanh(float x){
    return 1.f - 2.f / (__expf(2.f * x) + 1.f);   // stable at both infinities
}
__device__ __forceinline__ unsigned pack_bf16x2(float lo, float hi){
    unsigned r;
    asm("cvt.rn.bf16x2.f32 %0, %1, %2;" : "=r"(r) : "f"(hi), "f"(lo));
    return r;
}
__device__ __forceinline__ unsigned short to_bf16(float x){
    unsigned short h;
    asm("cvt.rn.bf16.f32 %0, %1;" : "=h"(h) : "f"(x));
    return h;
}

__global__ void init_bar(){
    int i = threadIdx.x;
    unsigned* f = &g_flag[0][0][0];
    for (int idx = i; idx < 2 * 64 * 32; idx += 256) f[idx] = 0u;
}

// ---------------- shared bf16 mma helper ----------------
__device__ __forceinline__ void mma_bf16(
    float &d0, float &d1, float &d2, float &d3,
    unsigned a0, unsigned a1, unsigned a2, unsigned a3,
    unsigned b0, unsigned b1)
{
    asm volatile(
        "mma.sync.aligned.m16n8k16.row.col.f32.bf16.bf16.f32 "
        "{%0,%1,%2,%3}, {%4,%5,%6,%7}, {%8,%9}, {%0,%1,%2,%3};"
        : "+f"(d0), "+f"(d1), "+f"(d2), "+f"(d3)
        : "r"(a0), "r"(a1), "r"(a2), "r"(a3), "r"(b0), "r"(b1));
}

// ---------------- Phase A: G = X @ W_ih^T + b via bf16 tensor cores ----------------
__global__ __launch_bounds__(256) void proj_gemm_tc(
    const float* __restrict__ x,
    const float* __restrict__ Wf, const float* __restrict__ bf,
    const float* __restrict__ Wb, const float* __restrict__ bb)
{
    __shared__ unsigned As[128 * 20];   // [m][k-pair], stride 20 words
    __shared__ unsigned Bs[128 * 20];   // [n][k-pair]
    const int dir = blockIdx.z;
    const float* W    = dir ? Wb : Wf;
    const float* bias = dir ? bb : bf;
    const int tid = threadIdx.x;
    const int mBase = blockIdx.y << 7;
    const int nBase = blockIdx.x << 7;
    const int warp = tid >> 5, lane = tid & 31;
    const int wm = warp & 1;
    const int wn = warp >> 1;
    const int lr = lane >> 2;
    const int lc = lane & 3;

    const int grow = tid >> 1;
    const int gq   = (tid & 1) << 4;

    const float* xp = x + (size_t)(mBase + grow) * 1024 + gq;
    const float* wp = W + (size_t)(nBase + grow) * 1024 + gq;

    float acc[4][4][4];
#pragma unroll
    for (int i = 0; i < 4; ++i)
#pragma unroll
        for (int j = 0; j < 4; ++j)
#pragma unroll
            for (int c = 0; c < 4; ++c) acc[i][j][c] = 0.f;

    float4 ax[4], bx[4];
#pragma unroll
    for (int i = 0; i < 4; ++i){
        ax[i] = *(const float4*)(xp + (i << 2));
        bx[i] = *(const float4*)(wp + (i << 2));
    }

    for (int kt = 0; kt < 32; ++kt){
        __syncthreads();
        {
            unsigned* ad = &As[grow * 20 + ((tid & 1) << 3)];
            unsigned* bd = &Bs[grow * 20 + ((tid & 1) << 3)];
            uint4 pa0 = make_uint4(pack_bf16x2(ax[0].x, ax[0].y), pack_bf16x2(ax[0].z, ax[0].w),
                                   pack_bf16x2(ax[1].x, ax[1].y), pack_bf16x2(ax[1].z, ax[1].w));
            uint4 pa1 = make_uint4(pack_bf16x2(ax[2].x, ax[2].y), pack_bf16x2(ax[2].z, ax[2].w),
                                   pack_bf16x2(ax[3].x, ax[3].y), pack_bf16x2(ax[3].z, ax[3].w));
            uint4 pb0 = make_uint4(pack_bf16x2(bx[0].x, bx[0].y), pack_bf16x2(bx[0].z, bx[0].w),
                                   pack_bf16x2(bx[1].x, bx[1].y), pack_bf16x2(bx[1].z, bx[1].w));
            uint4 pb1 = make_uint4(pack_bf16x2(bx[2].x, bx[2].y), pack_bf16x2(bx[2].z, bx[2].w),
                                   pack_bf16x2(bx[3].x, bx[3].y), pack_bf16x2(bx[3].z, bx[3].w));
            *(uint4*)&ad[0] = pa0;
            *(uint4*)&ad[4] = pa1;
            *(uint4*)&bd[0] = pb0;
            *(uint4*)&bd[4] = pb1;
        }
        __syncthreads();
        if (kt < 31){
#pragma unroll
            for (int i = 0; i < 4; ++i){
                ax[i] = *(const float4*)(xp + (kt + 1) * 32 + (i << 2));
                bx[i] = *(const float4*)(wp + (kt + 1) * 32 + (i << 2));
            }
        }
#pragma unroll
        for (int kg = 0; kg < 2; ++kg){
            const int kw = kg << 3;
            unsigned af[4][4];
#pragma unroll
            for (int mt = 0; mt < 4; ++mt){
                const int m0 = (wm << 6) + (mt << 4);
                af[mt][0] = As[(m0 + lr)     * 20 + kw + lc];
                af[mt][1] = As[(m0 + lr + 8) * 20 + kw + lc];
                af[mt][2] = As[(m0 + lr)     * 20 + kw + 4 + lc];
                af[mt][3] = As[(m0 + lr + 8) * 20 + kw + 4 + lc];
            }
            unsigned bfr[4][2];
#pragma unroll
            for (int nt = 0; nt < 4; ++nt){
                const int n0 = (wn << 5) + (nt << 3);
                bfr[nt][0] = Bs[(n0 + lr) * 20 + kw + lc];
                bfr[nt][1] = Bs[(n0 + lr) * 20 + kw + 4 + lc];
            }
#pragma unroll
            for (int mt = 0; mt < 4; ++mt)
#pragma unroll
                for (int nt = 0; nt < 4; ++nt)
                    mma_bf16(acc[mt][nt][0], acc[mt][nt][1],
                             acc[mt][nt][2], acc[mt][nt][3],
                             af[mt][0], af[mt][1], af[mt][2], af[mt][3],
                             bfr[nt][0], bfr[nt][1]);
        }
    }

#pragma unroll
    for (int nt = 0; nt < 4; ++nt){
        const int gcol = nBase + (wn << 5) + (nt << 3) + (lc << 1);
        float2 bv = *(const float2*)(bias + gcol);
#pragma unroll
        for (int mt = 0; mt < 4; ++mt){
            const int grow0 = mBase + (wm << 6) + (mt << 4) + lr;
            float2 r0 = make_float2(acc[mt][nt][0] + bv.x, acc[mt][nt][1] + bv.y);
            float2 r1 = make_float2(acc[mt][nt][2] + bv.x, acc[mt][nt][3] + bv.y);
            *(float2*)(&g_G[dir][grow0][gcol])     = r0;
            *(float2*)(&g_G[dir][grow0 + 8][gcol]) = r1;
        }
    }
}

// ---------------- Phase B: persistent bidirectional LSTM (bf16 tensor cores) ----------------
// 128 blocks x 256 threads. Block: one dir, 16 units = 64 gate-rows.
// Warp (rt = w&3, kh = w>>2). Weights in smem as A-fragments (loaded once).
// B-fragments (h) loaded DIRECTLY from L2 into registers in mma layout — no smem
// staging, no staging sync. Ordering: each lane spin-acquires one of the 32
// producer blocks of its k-half, then __syncwarp() (memory-ordering among lanes)
// covers all producers. ONE __syncthreads per step (ds combine); ds double-buffered.
#define AFRAG_BYTES 131072
#define DS_OFF      131072
#define DS_BYTES    8192                          // 2 buffers x 4KB
#define SMEM_PERSIST (DS_OFF + DS_BYTES)          // 139264

__global__ __launch_bounds__(256) void lstm_persist(
    const float* __restrict__ Whf, const float* __restrict__ Whb,
    const int* __restrict__ lengths)
{
    extern __shared__ char smem[];

    const int blk = blockIdx.x;
    const int dir = blk >> 6;
    const int myblk = blk & 63;
    const int ub  = myblk << 4;
    const float* Wh = dir ? Whb : Whf;
    const int tid  = threadIdx.x;
    const int w    = tid >> 5;
    const int lane = tid & 31;
    const int rt   = w & 3;          // row-tile 0..3
    const int kh   = w >> 2;         // k-half 0..1
    const int lr   = lane >> 2;      // 0..7  (batch for B frag)
    const int lc   = lane & 3;

    // ---- preload weights into smem as bf16 A-fragments (one time) ----
    for (int s = tid; s < 32768; s += 256){
        int r  = s & 3;
        int ln = (s >> 2) & 31;
        int kt = (s >> 7) & 63;
        int rts = s >> 13;
        int rit  = (ln >> 2) + ((r & 1) << 3);
        int unit = (rts << 2) + (rit >> 2);
        int gate = rit & 3;
        int k    = (kt << 4) + ((ln & 3) << 1) + ((r >> 1) << 3);
        const float* wrow = Wh + (size_t)((gate << 10) + ub + unit) * 1024 + k;
        ((unsigned*)smem)[(((rts << 6) + kt) << 7) + (ln << 2) + r] =
            pack_bf16x2(wrow[0], wrow[1]);
    }

    // update-thread state (tid < 128): unit = tid>>3, batch = tid&7
    const int uu = tid >> 3;
    const int b  = tid & 7;
    const int lbmy = (tid < 128) ? lengths[b] : 0;
    float creg = 0.f, hreg = 0.f;

    // zero initial h (buffer 0)
    if (tid < 128) g_hb[0][dir][b][ub + uu] = 0;

    // per-lane producer flag: this warp's k-half needs blocks kh*32 .. kh*32+31
    const unsigned* lflag = &g_flag[dir][(kh << 5) + lane][0];
    unsigned* ownflag = &g_flag[dir][myblk][0];

    // publish initial h (counts as "h_0 available" = 4 arrivals)
    __syncthreads();   // weights staged + initial h written (block-wide ordering)
    if (tid == 0){
        asm volatile("red.release.gpu.global.add.u32 [%0], %1;"
                     :: "l"(ownflag), "r"(4u) : "memory");
    }

    const uint4* A4 = (const uint4*)smem + ((rt << 6) + (kh << 5)) * 32 + lane;
    float* ds = (float*)(smem + DS_OFF);
    // per-lane h base offset (elements): batch lr, k-half kh, column pair lc
    const int hoff = (lr << 10) + (kh << 9) + (lc << 1);

    for (int t = 0; t < 512; ++t){
        const int rbuf = t & 1, wbuf = rbuf ^ 1;
        float* dsb = ds + ((t & 1) << 10);   // this step's ds buffer

        // prefetch this step's G entries (DRAM latency hidden under spin+mma)
        float q0 = 0.f, q1 = 0.f, q2 = 0.f, q3 = 0.f;
        const bool act = (tid < 128) && (t < lbmy);
        int pos = 0;
        if (act){
            pos = dir ? (lbmy - 1 - t) : t;
            const int n = ub + uu;
            const float* Gp = &g_G[dir][(b << 9) + pos][0];
            q0 = Gp[n]; q1 = Gp[1024 + n]; q2 = Gp[2048 + n]; q3 = Gp[3072 + n];
        }

        // spin: each lane acquires one producer; syncwarp propagates to all lanes
        {
            const unsigned target = 4u * (unsigned)(t + 1);
            unsigned v;
            do {
                asm volatile("ld.acquire.gpu.global.u32 %0, [%1];"
                             : "=r"(v) : "l"(lflag) : "memory");
            } while (v < target);
        }
        __syncwarp();

        // load B-fragments (h_t) directly from L2 in mma layout
        const unsigned* hp = (const unsigned*)(&g_hb[rbuf][dir][0][0] + hoff);
        unsigned breg[64];
#pragma unroll
        for (int i = 0; i < 32; ++i){
            breg[(i << 1)]     = __ldcg(hp + (i << 3));
            breg[(i << 1) + 1] = __ldcg(hp + (i << 3) + 4);
        }

        // mma phase: 32 mma per warp, 4 independent accumulators
        float ac[4][4];
#pragma unroll
        for (int j = 0; j < 4; ++j){
            ac[j][0] = 0.f; ac[j][1] = 0.f; ac[j][2] = 0.f; ac[j][3] = 0.f;
        }
#pragma unroll 2
        for (int i8 = 0; i8 < 8; ++i8){
#pragma unroll
            for (int j = 0; j < 4; ++j){
                const int ktl = (i8 << 2) + j;
                uint4 a = A4[ktl << 5];
                mma_bf16(ac[j][0], ac[j][1], ac[j][2], ac[j][3],
                         a.x, a.y, a.z, a.w,
                         breg[ktl << 1], breg[(ktl << 1) + 1]);
            }
        }
        float c0 = ac[0][0] + ac[1][0] + ac[2][0] + ac[3][0];
        float c1 = ac[0][1] + ac[1][1] + ac[2][1] + ac[3][1];
        float c2 = ac[0][2] + ac[1][2] + ac[2][2] + ac[3][2];
        float c3 = ac[0][3] + ac[1][3] + ac[2][3] + ac[3][3];

        // write partial D to smem: dsb[kh][rt][row][batch]
        {
            float* dw = dsb + (kh << 9) + (rt << 7);
            const int g = lane >> 2, tt = lane & 3;
            *(float2*)&dw[(g << 3) + (tt << 1)]       = make_float2(c0, c1);
            *(float2*)&dw[((g + 8) << 3) + (tt << 1)] = make_float2(c2, c3);
        }
        __syncthreads();   // ds complete -> update may read

        // cell update + immediate per-warp publication
        if (tid < 128){
            const int rtt = uu >> 2;
            const int rb  = ((uu & 3) << 2);
            const float* d0p = dsb + (rtt << 7);
            const float* d1p = dsb + 512 + (rtt << 7);
            float gi = d0p[((rb + 0) << 3) + b] + d1p[((rb + 0) << 3) + b] + q0;
            float gf = d0p[((rb + 1) << 3) + b] + d1p[((rb + 1) << 3) + b] + q1;
            float gg = d0p[((rb + 2) << 3) + b] + d1p[((rb + 2) << 3) + b] + q2;
            float go = d0p[((rb + 3) << 3) + b] + d1p[((rb + 3) << 3) + b] + q3;
            if (act){
                float si = fast_sigmoid(gi);
                float sf = fast_sigmoid(gf);
                float tg = fast_tanh(gg);
                float so = fast_sigmoid(go);
                creg = sf * creg + si * tg;
                hreg = so * fast_tanh(creg);
                g_hout[dir][b][pos][ub + uu] = hreg;
            }
            g_hb[wbuf][dir][b][ub + uu] = to_bf16(hreg);   // carry when masked
            __syncwarp();          // order all 32 lanes' h stores before the add
            if (lane == 0){
                asm volatile("red.release.gpu.global.add.u32 [%0], %1;"
                             :: "l"(ownflag), "r"(1u) : "memory");
            }
        }
    }
}

// ---------------- Phase C1: emissions ----------------
__global__ void emit_kernel(const int* __restrict__ lengths,
                            const float* __restrict__ We,
                            const float* __restrict__ be)
{
    const int t = blockIdx.x, b = blockIdx.y;
    if (t >= lengths[b]) return;
    __shared__ float h[2048];
    const int tid = threadIdx.x;
    const float* hf = &g_hout[0][b][t][0];
    const float* hb = &g_hout[1][b][t][0];
    for (int j = tid; j < 1024; j += 128){
        h[j]        = hf[j];
        h[1024 + j] = hb[j];
    }
    __syncthreads();
    const int k = tid >> 3, sub = tid & 7;
    const float* wk = We + (k << 11);
    float s = 0.f;
    for (int j = (sub << 2); j < 2048; j += 32){
        float4 wv = *(const float4*)(wk + j);
        float4 hv = *(const float4*)(&h[j]);
        s += wv.x * hv.x + wv.y * hv.y + wv.z * hv.z + wv.w * hv.w;
    }
    s += __shfl_xor_sync(0xffffffffu, s, 4);
    s += __shfl_xor_sync(0xffffffffu, s, 2);
    s += __shfl_xor_sync(0xffffffffu, s, 1);
    if (sub == 0) g_emit[b][t][k] = s + be[k];
}

// ---------------- Phase C2: CRF gold score + forward algorithm ----------------
__global__ void crf_kernel(const int* __restrict__ tags,
                           const int* __restrict__ lengths,
                           const float* __restrict__ trans,
                           float* __restrict__ out)
{
    __shared__ float T[16][16];
    const int tid = threadIdx.x;
    T[tid >> 4][tid & 15] = trans[tid];
    __syncthreads();

    const int b = tid >> 5, lane = tid & 31;
    const int lb = lengths[b];
    const int* tg = tags + (b << 9);

    float sc = 0.f;
    for (int tt = lane; tt < lb; tt += 32){
        sc += g_emit[b][tt][tg[tt]];
        if (tt >= 1) sc += T[tg[tt - 1]][tg[tt]];
    }
#pragma unroll
    for (int o = 16; o; o >>= 1) sc += __shfl_xor_sync(0xffffffffu, sc, o);

    const int j = lane & 15;
    float d = (lane < 16) ? g_emit[b][0][j] : -3e38f;
    for (int tt = 1; tt < lb; ++tt){
        float v[16];
        float mx = -3e38f;
#pragma unroll
        for (int i = 0; i < 16; ++i){
            float di = __shfl_sync(0xffffffffu, d, i);
            v[i] = di + T[i][j];
            mx = fmaxf(mx, v[i]);
        }
        float ssum = 0.f;
#pragma unroll
        for (int i = 0; i < 16; ++i) ssum += __expf(v[i] - mx);
        float nd = mx + __logf(ssum) + g_emit[b][tt][j];
        if (lane < 16) d = nd;
    }

    float mz = d;
#pragma unroll
    for (int o = 8; o; o >>= 1) mz = fmaxf(mz, __shfl_xor_sync(0xffffffffu, mz, o));
    float zs = __expf(d - mz);
#pragma unroll
    for (int o = 8; o; o >>= 1) zs += __shfl_xor_sync(0xffffffffu, zs, o);
    float logZ = mz + __logf(zs);

    if (lane == 0) out[b] = logZ - sc;
}

// ---------------- launch ----------------
extern "C" void kernel_launch(void* const* d_in, const int* in_sizes, int n_in,
                              void* d_out, int out_size)
{
    (void)in_sizes; (void)n_in; (void)out_size;
    const float* x    = (const float*)d_in[0];
    const int*   tags = (const int*)  d_in[1];
    const int*   lens = (const int*)  d_in[2];
    const float* Wihf = (const float*)d_in[3];
    const float* Whhf = (const float*)d_in[4];
    const float* bf_  = (const float*)d_in[5];
    const float* Wihb = (const float*)d_in[6];
    const float* Whhb = (const float*)d_in[7];
    const float* bb_  = (const float*)d_in[8];
    const float* We   = (const float*)d_in[9];
    const float* be   = (const float*)d_in[10];
    const float* tr   = (const float*)d_in[11];
    float* out = (float*)d_out;

    cudaFuncSetAttribute(lstm_persist,
                         cudaFuncAttributeMaxDynamicSharedMemorySize, SMEM_PERSIST);

    init_bar<<<1, 256>>>();
    proj_gemm_tc<<<dim3(32, 32, 2), 256>>>(x, Wihf, bf_, Wihb, bb_);
    lstm_persist<<<128, 256, SMEM_PERSIST>>>(Whhf, Whhb, lens);
    emit_kernel<<<dim3(512, 8), 128>>>(lens, We, be);
    crf_kernel<<<1, 256>>>(tags, lens, tr, out);
}

// round 17
// speedup vs baseline: 3.7916x; 3.7916x over previous
#include <cuda_runtime.h>

// B=8, L=512, E=H=1024, K=16, 4H=4096
typedef unsigned long long u64;

// ---------------- scratch (static __device__; no allocations) ----------------
__device__ float g_G[2][4096][4096];                      // input projections + bias
__device__ __align__(16) unsigned short g_hb[2][2][8][1024]; // h double-buffered, bf16 [buf][dir][b][n]
__device__ float g_hout[2][8][512][1024];                 // h outputs at original positions (fp32)
__device__ float g_emit[8][512][16];                      // emissions
__device__ unsigned g_flag[2][64][32];                    // arrive-count flags (128B padded)

__device__ __forceinline__ float fast_sigmoid(float x){
    return 1.f / (1.f + __expf(-x));
}
__device__ __forceinline__ float fast_tanh(float x){
    return 1.f - 2.f / (__expf(2.f * x) + 1.f);   // stable at both infinities
}
__device__ __forceinline__ unsigned pack_bf16x2(float lo, float hi){
    unsigned r;
    asm("cvt.rn.bf16x2.f32 %0, %1, %2;" : "=r"(r) : "f"(hi), "f"(lo));
    return r;
}
__device__ __forceinline__ unsigned short to_bf16(float x){
    unsigned short h;
    asm("cvt.rn.bf16.f32 %0, %1;" : "=h"(h) : "f"(x));
    return h;
}

__global__ void init_bar(){
    int i = threadIdx.x;
    unsigned* f = &g_flag[0][0][0];
    for (int idx = i; idx < 2 * 64 * 32; idx += 256) f[idx] = 0u;
}

// ---------------- shared bf16 mma helper ----------------
__device__ __forceinline__ void mma_bf16(
    float &d0, float &d1, float &d2, float &d3,
    unsigned a0, unsigned a1, unsigned a2, unsigned a3,
    unsigned b0, unsigned b1)
{
    asm volatile(
        "mma.sync.aligned.m16n8k16.row.col.f32.bf16.bf16.f32 "
        "{%0,%1,%2,%3}, {%4,%5,%6,%7}, {%8,%9}, {%0,%1,%2,%3};"
        : "+f"(d0), "+f"(d1), "+f"(d2), "+f"(d3)
        : "r"(a0), "r"(a1), "r"(a2), "r"(a3), "r"(b0), "r"(b1));
}

// ---------------- Phase A: G = X @ W_ih^T + b via bf16 tensor cores ----------------
__global__ __launch_bounds__(256) void proj_gemm_tc(
    const float* __restrict__ x,
    const float* __restrict__ Wf, const float* __restrict__ bf,
    const float* __restrict__ Wb, const float* __restrict__ bb)
{
    __shared__ unsigned As[128 * 20];   // [m][k-pair], stride 20 words
    __shared__ unsigned Bs[128 * 20];   // [n][k-pair]
    const int dir = blockIdx.z;
    const float* W    = dir ? Wb : Wf;
    const float* bias = dir ? bb : bf;
    const int tid = threadIdx.x;
    const int mBase = blockIdx.y << 7;
    const int nBase = blockIdx.x << 7;
    const int warp = tid >> 5, lane = tid & 31;
    const int wm = warp & 1;
    const int wn = warp >> 1;
    const int lr = lane >> 2;
    const int lc = lane & 3;

    const int grow = tid >> 1;
    const int gq   = (tid & 1) << 4;

    const float* xp = x + (size_t)(mBase + grow) * 1024 + gq;
    const float* wp = W + (size_t)(nBase + grow) * 1024 + gq;

    float acc[4][4][4];
#pragma unroll
    for (int i = 0; i < 4; ++i)
#pragma unroll
        for (int j = 0; j < 4; ++j)
#pragma unroll
            for (int c = 0; c < 4; ++c) acc[i][j][c] = 0.f;

    float4 ax[4], bx[4];
#pragma unroll
    for (int i = 0; i < 4; ++i){
        ax[i] = *(const float4*)(xp + (i << 2));
        bx[i] = *(const float4*)(wp + (i << 2));
    }

    for (int kt = 0; kt < 32; ++kt){
        __syncthreads();
        {
            unsigned* ad = &As[grow * 20 + ((tid & 1) << 3)];
            unsigned* bd = &Bs[grow * 20 + ((tid & 1) << 3)];
            uint4 pa0 = make_uint4(pack_bf16x2(ax[0].x, ax[0].y), pack_bf16x2(ax[0].z, ax[0].w),
                                   pack_bf16x2(ax[1].x, ax[1].y), pack_bf16x2(ax[1].z, ax[1].w));
            uint4 pa1 = make_uint4(pack_bf16x2(ax[2].x, ax[2].y), pack_bf16x2(ax[2].z, ax[2].w),
                                   pack_bf16x2(ax[3].x, ax[3].y), pack_bf16x2(ax[3].z, ax[3].w));
            uint4 pb0 = make_uint4(pack_bf16x2(bx[0].x, bx[0].y), pack_bf16x2(bx[0].z, bx[0].w),
                                   pack_bf16x2(bx[1].x, bx[1].y), pack_bf16x2(bx[1].z, bx[1].w));
            uint4 pb1 = make_uint4(pack_bf16x2(bx[2].x, bx[2].y), pack_bf16x2(bx[2].z, bx[2].w),
                                   pack_bf16x2(bx[3].x, bx[3].y), pack_bf16x2(bx[3].z, bx[3].w));
            *(uint4*)&ad[0] = pa0;
            *(uint4*)&ad[4] = pa1;
            *(uint4*)&bd[0] = pb0;
            *(uint4*)&bd[4] = pb1;
        }
        __syncthreads();
        if (kt < 31){
#pragma unroll
            for (int i = 0; i < 4; ++i){
                ax[i] = *(const float4*)(xp + (kt + 1) * 32 + (i << 2));
                bx[i] = *(const float4*)(wp + (kt + 1) * 32 + (i << 2));
            }
        }
#pragma unroll
        for (int kg = 0; kg < 2; ++kg){
            const int kw = kg << 3;
            unsigned af[4][4];
#pragma unroll
            for (int mt = 0; mt < 4; ++mt){
                const int m0 = (wm << 6) + (mt << 4);
                af[mt][0] = As[(m0 + lr)     * 20 + kw + lc];
                af[mt][1] = As[(m0 + lr + 8) * 20 + kw + lc];
                af[mt][2] = As[(m0 + lr)     * 20 + kw + 4 + lc];
                af[mt][3] = As[(m0 + lr + 8) * 20 + kw + 4 + lc];
            }
            unsigned bfr[4][2];
#pragma unroll
            for (int nt = 0; nt < 4; ++nt){
                const int n0 = (wn << 5) + (nt << 3);
                bfr[nt][0] = Bs[(n0 + lr) * 20 + kw + lc];
                bfr[nt][1] = Bs[(n0 + lr) * 20 + kw + 4 + lc];
            }
#pragma unroll
            for (int mt = 0; mt < 4; ++mt)
#pragma unroll
                for (int nt = 0; nt < 4; ++nt)
                    mma_bf16(acc[mt][nt][0], acc[mt][nt][1],
                             acc[mt][nt][2], acc[mt][nt][3],
                             af[mt][0], af[mt][1], af[mt][2], af[mt][3],
                             bfr[nt][0], bfr[nt][1]);
        }
    }

#pragma unroll
    for (int nt = 0; nt < 4; ++nt){
        const int gcol = nBase + (wn << 5) + (nt << 3) + (lc << 1);
        float2 bv = *(const float2*)(bias + gcol);
#pragma unroll
        for (int mt = 0; mt < 4; ++mt){
            const int grow0 = mBase + (wm << 6) + (mt << 4) + lr;
            float2 r0 = make_float2(acc[mt][nt][0] + bv.x, acc[mt][nt][1] + bv.y);
            float2 r1 = make_float2(acc[mt][nt][2] + bv.x, acc[mt][nt][3] + bv.y);
            *(float2*)(&g_G[dir][grow0][gcol])     = r0;
            *(float2*)(&g_G[dir][grow0 + 8][gcol]) = r1;
        }
    }
}

// ---------------- Phase B: persistent bidirectional LSTM (bf16 tensor cores) ----------------
// 128 blocks x 256 threads. Block: one dir, 16 units = 64 gate-rows.
// Warp (rt = w&3, kh = w>>2). Weights preloaded ONCE into smem as A-fragments.
// h staged via smem (round-15 structure). ds is double-buffered and combined
// per-ROWTILE with a 64-thread named barrier (warp rt pairs with warp rt+4)
// instead of a block-wide sync: each rowtile's update+publication starts as
// soon as its own pair is done.
#define AFRAG_BYTES 131072
#define HS_OFF      131072
#define HS_STRIDE   2064
#define HS_BYTES    (8 * HS_STRIDE)
#define DS_OFF      (HS_OFF + HS_BYTES)
#define DS_BYTES    8192                           // 2 buffers x 4KB
#define SMEM_PERSIST (DS_OFF + DS_BYTES)           // 155776

__global__ __launch_bounds__(256) void lstm_persist(
    const float* __restrict__ Whf, const float* __restrict__ Whb,
    const int* __restrict__ lengths)
{
    extern __shared__ char smem[];

    const int blk = blockIdx.x;
    const int dir = blk >> 6;
    const int myblk = blk & 63;
    const int ub  = myblk << 4;
    const float* Wh = dir ? Whb : Whf;
    const int tid  = threadIdx.x;
    const int w    = tid >> 5;
    const int lane = tid & 31;
    const int rt   = w & 3;          // row-tile 0..3
    const int kh   = w >> 2;         // k-half 0..1

    // ---- preload weights into smem as bf16 A-fragments (one time) ----
    for (int s = tid; s < 32768; s += 256){
        int r  = s & 3;
        int ln = (s >> 2) & 31;
        int kt = (s >> 7) & 63;
        int rts = s >> 13;
        int rit  = (ln >> 2) + ((r & 1) << 3);
        int unit = (rts << 2) + (rit >> 2);
        int gate = rit & 3;
        int k    = (kt << 4) + ((ln & 3) << 1) + ((r >> 1) << 3);
        const float* wrow = Wh + (size_t)((gate << 10) + ub + unit) * 1024 + k;
        ((unsigned*)smem)[(((rts << 6) + kt) << 7) + (ln << 2) + r] =
            pack_bf16x2(wrow[0], wrow[1]);
    }

    // update-thread state (tid < 128): unit = tid>>3, batch = tid&7
    const int uu = tid >> 3;
    const int b  = tid & 7;
    const int lbmy = (tid < 128) ? lengths[b] : 0;
    float creg = 0.f, hreg = 0.f;

    // zero initial h (buffer 0)
    if (tid < 128) g_hb[0][dir][b][ub + uu] = 0;

    // producer block for my staging chunks
    const int prodblk = (tid & 127) >> 1;
    const unsigned* myflag = &g_flag[dir][prodblk][0];
    unsigned* ownflag = &g_flag[dir][myblk][0];

    // publish initial h (counts as "h_0 available" = 4 arrivals)
    __syncthreads();   // weights staged + initial h written (block-wide ordering)
    if (tid == 0){
        asm volatile("red.release.gpu.global.add.u32 [%0], %1;"
                     :: "l"(ownflag), "r"(4u) : "memory");
    }

    const uint4* A4 = (const uint4*)smem + ((rt << 6) + (kh << 5)) * 32 + lane;
    const char* hsb = smem + HS_OFF + (lane >> 2) * HS_STRIDE + (kh << 10)
                      + ((lane & 3) << 2);
    float* ds  = (float*)(smem + DS_OFF);

    for (int t = 0; t < 512; ++t){
        const int rbuf = t & 1, wbuf = rbuf ^ 1;
        float* dsb = ds + ((t & 1) << 10);   // this step's ds buffer

        // prefetch this step's G entries (DRAM latency hidden under spin+staging+mma)
        float q0 = 0.f, q1 = 0.f, q2 = 0.f, q3 = 0.f;
        const bool act = (tid < 128) && (t < lbmy);
        int pos = 0;
        if (act){
            pos = dir ? (lbmy - 1 - t) : t;
            const int n = ub + uu;
            const float* Gp = &g_G[dir][(b << 9) + pos][0];
            q0 = Gp[n]; q1 = Gp[1024 + n]; q2 = Gp[2048 + n]; q3 = Gp[3072 + n];
        }

        // spin until my producer finished step t-1 (h_t published)
        {
            const unsigned target = 4u * (unsigned)(t + 1);
            unsigned v;
            do {
                asm volatile("ld.acquire.gpu.global.u32 %0, [%1];"
                             : "=r"(v) : "l"(myflag) : "memory");
            } while (v < target);
        }

        // stage h_t (bf16, 16KB) from L2 into padded smem rows
        {
            const uint4* src = (const uint4*)&g_hb[rbuf][dir][0][0];
#pragma unroll
            for (int j = 0; j < 4; ++j){
                int idx = tid + (j << 8);
                int bb  = idx >> 7, k16 = idx & 127;
                uint4 v = __ldcg(src + (bb << 7) + k16);
                *(uint4*)(smem + HS_OFF + bb * HS_STRIDE + (k16 << 4)) = v;
            }
        }
        __syncthreads();   // staging complete -> mma may read hs
                           // (also orders prior-step dsb reuse: read@t-2 < this sync < write@t)

        // mma phase: 32 mma per warp, 4 independent accumulators
        float ac[4][4];
#pragma unroll
        for (int j = 0; j < 4; ++j){
            ac[j][0] = 0.f; ac[j][1] = 0.f; ac[j][2] = 0.f; ac[j][3] = 0.f;
        }
#pragma unroll 2
        for (int i8 = 0; i8 < 8; ++i8){
#pragma unroll
            for (int j = 0; j < 4; ++j){
                const int ktl = (i8 << 2) + j;
                uint4 a = A4[ktl << 5];
                unsigned b0 = *(const unsigned*)(hsb + (ktl << 5));
                unsigned b1 = *(const unsigned*)(hsb + (ktl << 5) + 16);
                mma_bf16(ac[j][0], ac[j][1], ac[j][2], ac[j][3],
                         a.x, a.y, a.z, a.w, b0, b1);
            }
        }
        float c0 = ac[0][0] + ac[1][0] + ac[2][0] + ac[3][0];
        float c1 = ac[0][1] + ac[1][1] + ac[2][1] + ac[3][1];
        float c2 = ac[0][2] + ac[1][2] + ac[2][2] + ac[3][2];
        float c3 = ac[0][3] + ac[1][3] + ac[2][3] + ac[3][3];

        // write partial D to smem: dsb[kh][rt][row][batch]
        {
            float* dw = dsb + (kh << 9) + (rt << 7);
            const int g = lane >> 2, tt = lane & 3;
            *(float2*)&dw[(g << 3) + (tt << 1)]       = make_float2(c0, c1);
            *(float2*)&dw[((g + 8) << 3) + (tt << 1)] = make_float2(c2, c3);
        }
        // per-rowtile combine: warp rt (kh=0) pairs with warp rt+4 (kh=1)
        asm volatile("bar.sync %0, 64;" :: "r"(rt + 1) : "memory");

        // cell update + immediate per-warp publication (update warps = kh0 warps)
        if (tid < 128){
            const int rtt = uu >> 2;               // == w for these threads
            const int rb  = ((uu & 3) << 2);
            const float* d0p = dsb + (rtt << 7);
            const float* d1p = dsb + 512 + (rtt << 7);
            float gi = d0p[((rb + 0) << 3) + b] + d1p[((rb + 0) << 3) + b] + q0;
            float gf = d0p[((rb + 1) << 3) + b] + d1p[((rb + 1) << 3) + b] + q1;
            float gg = d0p[((rb + 2) << 3) + b] + d1p[((rb + 2) << 3) + b] + q2;
            float go = d0p[((rb + 3) << 3) + b] + d1p[((rb + 3) << 3) + b] + q3;
            if (act){
                float si = fast_sigmoid(gi);
                float sf = fast_sigmoid(gf);
                float tg = fast_tanh(gg);
                float so = fast_sigmoid(go);
                creg = sf * creg + si * tg;
                hreg = so * fast_tanh(creg);
                g_hout[dir][b][pos][ub + uu] = hreg;
            }
            g_hb[wbuf][dir][b][ub + uu] = to_bf16(hreg);   // carry when masked
            __syncwarp();          // order all 32 lanes' h stores before the add
            if (lane == 0){
                asm volatile("red.release.gpu.global.add.u32 [%0], %1;"
                             :: "l"(ownflag), "r"(1u) : "memory");
            }
        }
    }
}

// ---------------- Phase C1: emissions ----------------
__global__ void emit_kernel(const int* __restrict__ lengths,
                            const float* __restrict__ We,
                            const float* __restrict__ be)
{
    const int t = blockIdx.x, b = blockIdx.y;
    if (t >= lengths[b]) return;
    __shared__ float h[2048];
    const int tid = threadIdx.x;
    const float* hf = &g_hout[0][b][t][0];
    const float* hb = &g_hout[1][b][t][0];
    for (int j = tid; j < 1024; j += 128){
        h[j]        = hf[j];
        h[1024 + j] = hb[j];
    }
    __syncthreads();
    const int k = tid >> 3, sub = tid & 7;
    const float* wk = We + (k << 11);
    float s = 0.f;
    for (int j = (sub << 2); j < 2048; j += 32){
        float4 wv = *(const float4*)(wk + j);
        float4 hv = *(const float4*)(&h[j]);
        s += wv.x * hv.x + wv.y * hv.y + wv.z * hv.z + wv.w * hv.w;
    }
    s += __shfl_xor_sync(0xffffffffu, s, 4);
    s += __shfl_xor_sync(0xffffffffu, s, 2);
    s += __shfl_xor_sync(0xffffffffu, s, 1);
    if (sub == 0) g_emit[b][t][k] = s + be[k];
}

// ---------------- Phase C2: CRF gold score + forward algorithm ----------------
__global__ void crf_kernel(const int* __restrict__ tags,
                           const int* __restrict__ lengths,
                           const float* __restrict__ trans,
                           float* __restrict__ out)
{
    __shared__ float T[16][16];
    const int tid = threadIdx.x;
    T[tid >> 4][tid & 15] = trans[tid];
    __syncthreads();

    const int b = tid >> 5, lane = tid & 31;
    const int lb = lengths[b];
    const int* tg = tags + (b << 9);

    float sc = 0.f;
    for (int tt = lane; tt < lb; tt += 32){
        sc += g_emit[b][tt][tg[tt]];
        if (tt >= 1) sc += T[tg[tt - 1]][tg[tt]];
    }
#pragma unroll
    for (int o = 16; o; o >>= 1) sc += __shfl_xor_sync(0xffffffffu, sc, o);

    const int j = lane & 15;
    float d = (lane < 16) ? g_emit[b][0][j] : -3e38f;
    for (int tt = 1; tt < lb; ++tt){
        float v[16];
        float mx = -3e38f;
#pragma unroll
        for (int i = 0; i < 16; ++i){
            float di = __shfl_sync(0xffffffffu, d, i);
            v[i] = di + T[i][j];
            mx = fmaxf(mx, v[i]);
        }
        float ssum = 0.f;
#pragma unroll
        for (int i = 0; i < 16; ++i) ssum += __expf(v[i] - mx);
        float nd = mx + __logf(ssum) + g_emit[b][tt][j];
        if (lane < 16) d = nd;
    }

    float mz = d;
#pragma unroll
    for (int o = 8; o; o >>= 1) mz = fmaxf(mz, __shfl_xor_sync(0xffffffffu, mz, o));
    float zs = __expf(d - mz);
#pragma unroll
    for (int o = 8; o; o >>= 1) zs += __shfl_xor_sync(0xffffffffu, zs, o);
    float logZ = mz + __logf(zs);

    if (lane == 0) out[b] = logZ - sc;
}

// ---------------- launch ----------------
extern "C" void kernel_launch(void* const* d_in, const int* in_sizes, int n_in,
                              void* d_out, int out_size)
{
    (void)in_sizes; (void)n_in; (void)out_size;
    const float* x    = (const float*)d_in[0];
    const int*   tags = (const int*)  d_in[1];
    const int*   lens = (const int*)  d_in[2];
    const float* Wihf = (const float*)d_in[3];
    const float* Whhf = (const float*)d_in[4];
    const float* bf_  = (const float*)d_in[5];
    const float* Wihb = (const float*)d_in[6];
    const float* Whhb = (const float*)d_in[7];
    const float* bb_  = (const float*)d_in[8];
    const float* We   = (const float*)d_in[9];
    const float* be   = (const float*)d_in[10];
    const float* tr   = (const float*)d_in[11];
    float* out = (float*)d_out;

    cudaFuncSetAttribute(lstm_persist,
                         cudaFuncAttributeMaxDynamicSharedMemorySize, SMEM_PERSIST);

    init_bar<<<1, 256>>>();
    proj_gemm_tc<<<dim3(32, 32, 2), 256>>>(x, Wihf, bf_, Wihb, bb_);
    lstm_persist<<<128, 256, SMEM_PERSIST>>>(Whhf, Whhb, lens);
    emit_kernel<<<dim3(512, 8), 128>>>(lens, We, be);
    crf_kernel<<<1, 256>>>(tags, lens, tr, out);
}